// round 3
// baseline (speedup 1.0000x reference)
#include <cuda_runtime.h>
#include <cuda_bf16.h>
#include <math.h>
#include <stdint.h>

// Shapes: B=4, N=256, F=64, H=256, A=16, T=3
#define Bn 4
#define Nn 256
#define Fn 64
#define Hn 256
#define An 16
#define Tn 3
#define BN (Bn*Nn)       // 1024
#define NC 1280          // fused cols: 256(hi)+256(hj)+768(gh)

typedef __nv_bfloat16 bf16;

// ---------------- scratch (device globals) -----------------------------------
__device__ float d_h   [BN*Hn];
__device__ float d_big [BN*NC];
__device__ float d_deg [BN];
__device__ float d_gi  [BN*3*Hn];
__device__ float d_Wc  [Hn*3*Hn];
__device__ float d_bc  [3*Hn];
__device__ float d_bcat[NC];

// bf16 split planes. A-operand: row-major MxK. B-operand: N-major [N][K].
__device__ bf16 d_Xh [BN*Fn],    d_Xl [BN*Fn];      // A: X
__device__ bf16 d_th [BN*Hn],    d_tl [BN*Hn];      // A: pre-MLP hidden
__device__ bf16 d_hh [BN*Hn],    d_hl [BN*Hn];      // A: h
__device__ bf16 d_ah [BN*Hn],    d_al [BN*Hn];      // A: agg0
__device__ bf16 d_M2h[Hn*Hn],    d_M2l[Hn*Hn];      // A: msg_W2
__device__ bf16 d_W1th[Hn*Fn],   d_W1tl[Hn*Fn];     // B: pre_W1^T  [256][64]
__device__ bf16 d_W2th[Hn*Hn],   d_W2tl[Hn*Hn];     // B: pre_W2^T  [256][256]
__device__ bf16 d_Wihth[768*Hn], d_Wihtl[768*Hn];   // B: gru_Wih^T [768][256]
__device__ bf16 d_Wcth[NC*Hn],   d_Wctl[NC*Hn];     // B: Wcat^T    [1280][256]
__device__ bf16 d_Wcch[768*Hn],  d_Wccl[768*Hn];    // B: Wc^T      [768][256]

__device__ __forceinline__ void split2(float x, bf16& h, bf16& l) {
    h = __float2bfloat16(x);
    l = __float2bfloat16(x - __bfloat162float(h));
}

// ---------------- converts ---------------------------------------------------
// A-layout split: dst[idx] = split(src[idx])
__global__ void convA(const float* __restrict__ src, bf16* __restrict__ dh,
                      bf16* __restrict__ dl, int n)
{
    int i = blockIdx.x * 256 + threadIdx.x;
    if (i < n) split2(src[i], dh[i], dl[i]);
}

// B-layout split (transpose): src KxN row-major -> dst [N][K]
__global__ void convB(const float* __restrict__ src, bf16* __restrict__ dh,
                      bf16* __restrict__ dl, int K, int N)
{
    int i = blockIdx.x * 256 + threadIdx.x;
    if (i >= K * N) return;
    int n = i / K, k = i % K;
    split2(src[(size_t)k * N + n], dh[i], dl[i]);
}

// Wcat^T planes [1280][256] from msg_W1 (512x256) and Whh (256x768), + bcat
__global__ void repackWcat(const float* __restrict__ msgW1, const float* __restrict__ Whh,
                           const float* __restrict__ msgb1, const float* __restrict__ bhh,
                           bf16* __restrict__ dh, bf16* __restrict__ dl,
                           float* __restrict__ bcat)
{
    int i = blockIdx.x * 256 + threadIdx.x;      // over NC*Hn
    int n = i / Hn, k = i % Hn;
    float v;
    if (n < 256)      v = msgW1[(size_t)k * Hn + n];
    else if (n < 512) v = msgW1[(size_t)(256 + k) * Hn + (n - 256)];
    else              v = Whh[(size_t)k * 768 + (n - 512)];
    split2(v, dh[i], dl[i]);
    if (i < NC)
        bcat[i] = i < 256 ? msgb1[i] : (i < 512 ? 0.f : bhh[i - 512]);
}

// ---------------- split-bf16 tensor-core GEMM --------------------------------
// C[M,N] = f( (Ah+Al)[MxK] @ (Bh+Bl)^T[[N][K]] + bias + rowS*colV )
// 3-product: Ah*Bh + Ah*Bl + Al*Bh, fp32 accum. CTA 128x128, 8 warps (64x32 each).
__device__ __forceinline__ void cpa16(void* s, const void* g) {
    uint32_t sa = (uint32_t)__cvta_generic_to_shared(s);
    asm volatile("cp.async.ca.shared.global [%0], [%1], 16;" :: "r"(sa), "l"(g));
}
#define MMA_BF16(ACC, A0,A1,A2,A3, B0,B1)                                    \
    asm volatile("mma.sync.aligned.m16n8k16.row.col.f32.bf16.bf16.f32 "      \
        "{%0,%1,%2,%3}, {%4,%5,%6,%7}, {%8,%9}, {%0,%1,%2,%3};"              \
        : "+f"((ACC)[0]), "+f"((ACC)[1]), "+f"((ACC)[2]), "+f"((ACC)[3])     \
        : "r"(A0), "r"(A1), "r"(A2), "r"(A3), "r"(B0), "r"(B1))

__global__ void __launch_bounds__(256)
gemm_tc(const bf16* __restrict__ Ah, const bf16* __restrict__ Al,
        const bf16* __restrict__ Bh, const bf16* __restrict__ Bl,
        const float* __restrict__ bias, const float* __restrict__ rowS,
        const float* __restrict__ colV, float* __restrict__ C,
        bf16* __restrict__ Ch, bf16* __restrict__ Cl,
        int M, int N, int K, int doRelu)
{
    __shared__ bf16 sAh[2][128*16], sAl[2][128*16];
    __shared__ bf16 sBh[2][128*16], sBl[2][128*16];

    int tid = threadIdx.x;
    int l = tid & 31, w = tid >> 5;
    int wm = w >> 2, wn = w & 3;                // warp grid 2x4
    int row0 = blockIdx.y * 128, col0 = blockIdx.x * 128;

    int lr = tid >> 1, lh = (tid & 1) << 3;     // loader: row 0..127, 8-elem half
    const bf16* gAh = Ah + (size_t)(row0 + lr) * K + lh;
    const bf16* gAl = Al + (size_t)(row0 + lr) * K + lh;
    const bf16* gBh = Bh + (size_t)(col0 + lr) * K + lh;
    const bf16* gBl = Bl + (size_t)(col0 + lr) * K + lh;
    int soff = lr * 16 + lh;

    float acc[4][4][4];
    #pragma unroll
    for (int a = 0; a < 4; a++)
        #pragma unroll
        for (int b = 0; b < 4; b++)
            #pragma unroll
            for (int c = 0; c < 4; c++) acc[a][b][c] = 0.f;

    int nch = K >> 4;
    // issue chunk 0
    cpa16(&sAh[0][soff], gAh); cpa16(&sAl[0][soff], gAl);
    cpa16(&sBh[0][soff], gBh); cpa16(&sBl[0][soff], gBl);
    asm volatile("cp.async.commit_group;");

    for (int ch = 0; ch < nch; ch++) {
        int buf = ch & 1;
        if (ch + 1 < nch) {
            int nb = buf ^ 1, ko = (ch + 1) << 4;
            cpa16(&sAh[nb][soff], gAh + ko); cpa16(&sAl[nb][soff], gAl + ko);
            cpa16(&sBh[nb][soff], gBh + ko); cpa16(&sBl[nb][soff], gBl + ko);
            asm volatile("cp.async.commit_group;");
            asm volatile("cp.async.wait_group 1;");
        } else {
            asm volatile("cp.async.wait_group 0;");
        }
        __syncthreads();

        const uint32_t* Awh = (const uint32_t*)sAh[buf];
        const uint32_t* Awl = (const uint32_t*)sAl[buf];
        const uint32_t* Bwh = (const uint32_t*)sBh[buf];
        const uint32_t* Bwl = (const uint32_t*)sBl[buf];

        // B frags for this warp's 4 n-tiles
        uint32_t bh[4][2], bl[4][2];
        #pragma unroll
        for (int nt = 0; nt < 4; nt++) {
            int base = (wn * 32 + nt * 8 + (l >> 2)) * 8 + (l & 3);
            bh[nt][0] = Bwh[base]; bh[nt][1] = Bwh[base + 4];
            bl[nt][0] = Bwl[base]; bl[nt][1] = Bwl[base + 4];
        }
        #pragma unroll
        for (int mt = 0; mt < 4; mt++) {
            int base = (wm * 64 + mt * 16 + (l >> 2)) * 8 + (l & 3);
            uint32_t ah0 = Awh[base],      ah1 = Awh[base + 64];
            uint32_t ah2 = Awh[base + 4],  ah3 = Awh[base + 68];
            uint32_t al0 = Awl[base],      al1 = Awl[base + 64];
            uint32_t al2 = Awl[base + 4],  al3 = Awl[base + 68];
            #pragma unroll
            for (int nt = 0; nt < 4; nt++) {
                MMA_BF16(acc[mt][nt], ah0, ah1, ah2, ah3, bh[nt][0], bh[nt][1]);
                MMA_BF16(acc[mt][nt], ah0, ah1, ah2, ah3, bl[nt][0], bl[nt][1]);
                MMA_BF16(acc[mt][nt], al0, al1, al2, al3, bh[nt][0], bh[nt][1]);
            }
        }
        __syncthreads();
    }

    // epilogue
    #pragma unroll
    for (int mt = 0; mt < 4; mt++) {
        int r0 = row0 + wm * 64 + mt * 16 + (l >> 2);
        #pragma unroll
        for (int nt = 0; nt < 4; nt++) {
            int c0 = col0 + wn * 32 + nt * 8 + ((l & 3) << 1);
            #pragma unroll
            for (int e = 0; e < 4; e++) {
                int r = r0 + (e >> 1) * 8;
                int c = c0 + (e & 1);
                float v = acc[mt][nt][e];
                if (bias) v += bias[c];
                if (rowS) v += rowS[r] * colV[c];
                if (doRelu) v = fmaxf(v, 0.f);
                size_t o = (size_t)r * N + c;
                C[o] = v;
                if (Ch) split2(v, Ch[o], Cl[o]);
            }
        }
    }
}

// ---------------- E-aggregation ----------------------------------------------
// agg0[b,i,h] = sum_j adj * relu(hi'[i,h] + hj[j,h]); hi' at big[:,0:256] (b1 folded)
#define IT 8
__global__ void eagg(const float* __restrict__ big, const int* __restrict__ adj,
                     bf16* __restrict__ aggh, bf16* __restrict__ aggl,
                     float* __restrict__ deg)
{
    int b  = blockIdx.y;
    int i0 = blockIdx.x * IT;
    int h  = threadIdx.x;

    __shared__ float adjf[Nn][IT];   // [j][t] for float4 broadcast reads

    float hir[IT], acc[IT];
    #pragma unroll
    for (int t = 0; t < IT; t++) {
        adjf[h][t] = (float)adj[((size_t)(b * Nn + i0 + t)) * Nn + h];
        hir[t] = big[((size_t)(b * Nn + i0 + t)) * NC + h];
        acc[t] = 0.f;
    }
    __syncthreads();

    const float* hjb = big + (size_t)b * Nn * NC + 256;
    #pragma unroll 2
    for (int j = 0; j < Nn; j++) {
        float hjv = hjb[(size_t)j * NC + h];
        float4 a04 = *(float4*)&adjf[j][0];
        float4 a47 = *(float4*)&adjf[j][4];
        acc[0] += a04.x * fmaxf(hir[0] + hjv, 0.f);
        acc[1] += a04.y * fmaxf(hir[1] + hjv, 0.f);
        acc[2] += a04.z * fmaxf(hir[2] + hjv, 0.f);
        acc[3] += a04.w * fmaxf(hir[3] + hjv, 0.f);
        acc[4] += a47.x * fmaxf(hir[4] + hjv, 0.f);
        acc[5] += a47.y * fmaxf(hir[5] + hjv, 0.f);
        acc[6] += a47.z * fmaxf(hir[6] + hjv, 0.f);
        acc[7] += a47.w * fmaxf(hir[7] + hjv, 0.f);
    }

    #pragma unroll
    for (int t = 0; t < IT; t++) {
        size_t o = ((size_t)(b * Nn + i0 + t)) * Hn + h;
        split2(acc[t], aggh[o], aggl[o]);
    }

    if (h < IT) {
        float s = 0.f;
        for (int j = 0; j < Nn; j++) s += adjf[j][h];
        deg[b * Nn + i0 + h] = s;
    }
}

// ---------------- bc = msg_b2 @ gru_Wih --------------------------------------
__global__ void bck(const float* __restrict__ b2, const float* __restrict__ Wih,
                    float* __restrict__ bc)
{
    int warp = (blockIdx.x * blockDim.x + threadIdx.x) >> 5;
    int lane = threadIdx.x & 31;
    float s = 0.f;
    for (int k = lane; k < Hn; k += 32)
        s += b2[k] * Wih[(size_t)k * 768 + warp];
    #pragma unroll
    for (int o = 16; o; o >>= 1) s += __shfl_xor_sync(0xffffffffu, s, o);
    if (lane == 0) bc[warp] = s;
}

// ---------------- GRU update + bf16 re-split of h ----------------------------
__global__ void gru(const float* __restrict__ gi, const float* __restrict__ big,
                    float* __restrict__ h, bf16* __restrict__ hh, bf16* __restrict__ hl)
{
    int idx = blockIdx.x * 256 + threadIdx.x;
    int m = idx >> 8, c = idx & 255;
    const float* gim = gi  + (size_t)m * 768;
    const float* ghm = big + (size_t)m * NC + 512;
    float ir = gim[c], iz = gim[c + 256], in = gim[c + 512];
    float hr = ghm[c], hz = ghm[c + 256], hn = ghm[c + 512];
    float r = 1.f / (1.f + __expf(-(ir + hr)));
    float z = 1.f / (1.f + __expf(-(iz + hz)));
    float n = tanhf(in + r * hn);
    float hv = (1.f - z) * n + z * h[idx];
    h[idx] = hv;
    split2(hv, hh[idx], hl[idx]);
}

// ---------------- readout ----------------------------------------------------
__global__ void readout(const float* __restrict__ h,
                        const float* __restrict__ W1, const float* __restrict__ b1,
                        const float* __restrict__ W2, const float* __restrict__ b2,
                        float* __restrict__ out)
{
    __shared__ float gsh[Bn][Hn];
    __shared__ float hsh[Bn][Hn];
    int t = threadIdx.x;
    for (int b = 0; b < Bn; b++) {
        float s = 0.f;
        for (int i = 0; i < Nn; i++) s += h[((size_t)(b * Nn + i)) * Hn + t];
        gsh[b][t] = s;
    }
    __syncthreads();
    for (int b = 0; b < Bn; b++) {
        float s = b1[t];
        for (int k = 0; k < Hn; k++) s += gsh[b][k] * W1[(size_t)k * Hn + t];
        hsh[b][t] = fmaxf(s, 0.f);
    }
    __syncthreads();
    if (t < Bn * An) {
        int b = t >> 4, a = t & 15;
        float s = b2[a];
        for (int k = 0; k < Hn; k++) s += hsh[b][k] * W2[(size_t)k * An + a];
        out[b * An + a] = s;
    }
}

// ---------------- host launch ------------------------------------------------
extern "C" void kernel_launch(void* const* d_in, const int* in_sizes, int n_in,
                              void* d_out, int out_size)
{
    const float* X       = (const float*)d_in[0];
    const int*   adj     = (const int*)  d_in[1];
    const float* pre_W1  = (const float*)d_in[2];
    const float* pre_b1  = (const float*)d_in[3];
    const float* pre_W2  = (const float*)d_in[4];
    const float* pre_b2  = (const float*)d_in[5];
    const float* msg_W1  = (const float*)d_in[6];
    const float* msg_b1  = (const float*)d_in[7];
    const float* msg_W2  = (const float*)d_in[8];
    const float* msg_b2  = (const float*)d_in[9];
    const float* gru_Wih = (const float*)d_in[10];
    const float* gru_Whh = (const float*)d_in[11];
    const float* gru_bih = (const float*)d_in[12];
    const float* gru_bhh = (const float*)d_in[13];
    const float* ro_W1   = (const float*)d_in[14];
    const float* ro_b1   = (const float*)d_in[15];
    const float* ro_W2   = (const float*)d_in[16];
    const float* ro_b2   = (const float*)d_in[17];

    float *h, *big, *deg, *gi, *Wc, *bc, *bcat;
    bf16 *Xh,*Xl,*th,*tl,*hh,*hl,*ah,*al,*M2h,*M2l;
    bf16 *W1th,*W1tl,*W2th,*W2tl,*Wihth,*Wihtl,*Wcth,*Wctl,*Wcch,*Wccl;
    cudaGetSymbolAddress((void**)&h,    d_h);
    cudaGetSymbolAddress((void**)&big,  d_big);
    cudaGetSymbolAddress((void**)&deg,  d_deg);
    cudaGetSymbolAddress((void**)&gi,   d_gi);
    cudaGetSymbolAddress((void**)&Wc,   d_Wc);
    cudaGetSymbolAddress((void**)&bc,   d_bc);
    cudaGetSymbolAddress((void**)&bcat, d_bcat);
    cudaGetSymbolAddress((void**)&Xh,   d_Xh);   cudaGetSymbolAddress((void**)&Xl,  d_Xl);
    cudaGetSymbolAddress((void**)&th,   d_th);   cudaGetSymbolAddress((void**)&tl,  d_tl);
    cudaGetSymbolAddress((void**)&hh,   d_hh);   cudaGetSymbolAddress((void**)&hl,  d_hl);
    cudaGetSymbolAddress((void**)&ah,   d_ah);   cudaGetSymbolAddress((void**)&al,  d_al);
    cudaGetSymbolAddress((void**)&M2h,  d_M2h);  cudaGetSymbolAddress((void**)&M2l, d_M2l);
    cudaGetSymbolAddress((void**)&W1th, d_W1th); cudaGetSymbolAddress((void**)&W1tl,d_W1tl);
    cudaGetSymbolAddress((void**)&W2th, d_W2th); cudaGetSymbolAddress((void**)&W2tl,d_W2tl);
    cudaGetSymbolAddress((void**)&Wihth,d_Wihth);cudaGetSymbolAddress((void**)&Wihtl,d_Wihtl);
    cudaGetSymbolAddress((void**)&Wcth, d_Wcth); cudaGetSymbolAddress((void**)&Wctl,d_Wctl);
    cudaGetSymbolAddress((void**)&Wcch, d_Wcch); cudaGetSymbolAddress((void**)&Wccl,d_Wccl);

    // one-time converts / repacks
    convA<<<(BN*Fn+255)/256, 256>>>(X, Xh, Xl, BN*Fn);
    convA<<<(Hn*Hn+255)/256, 256>>>(msg_W2, M2h, M2l, Hn*Hn);
    convB<<<(Fn*Hn+255)/256, 256>>>(pre_W1, W1th, W1tl, Fn, Hn);
    convB<<<(Hn*Hn+255)/256, 256>>>(pre_W2, W2th, W2tl, Hn, Hn);
    convB<<<(Hn*768+255)/256, 256>>>(gru_Wih, Wihth, Wihtl, Hn, 768);
    repackWcat<<<NC*Hn/256, 256>>>(msg_W1, gru_Whh, msg_b1, gru_bhh, Wcth, Wctl, bcat);
    bck<<<96, 256>>>(msg_b2, gru_Wih, bc);

    // Wc = msg_W2 @ gru_Wih (fp32 out), then split to B-layout
    gemm_tc<<<dim3(768/128, Hn/128), 256>>>(M2h, M2l, Wihth, Wihtl,
        nullptr, nullptr, nullptr, Wc, nullptr, nullptr, Hn, 768, Hn, 0);
    convB<<<(Hn*768+255)/256, 256>>>(Wc, Wcch, Wccl, Hn, 768);

    // pre-MLP
    gemm_tc<<<dim3(Hn/128, BN/128), 256>>>(Xh, Xl, W1th, W1tl,
        pre_b1, nullptr, nullptr, big, th, tl, BN, Hn, Fn, 1);
    gemm_tc<<<dim3(Hn/128, BN/128), 256>>>(th, tl, W2th, W2tl,
        pre_b2, nullptr, nullptr, h, hh, hl, BN, Hn, Hn, 0);

    for (int it = 0; it < Tn; it++) {
        // [hi+b1 | hj | gh+bhh] = h @ Wcat + bcat
        gemm_tc<<<dim3(NC/128, BN/128), 256>>>(hh, hl, Wcth, Wctl,
            bcat, nullptr, nullptr, big, nullptr, nullptr, BN, NC, Hn, 0);
        eagg<<<dim3(Nn/IT, Bn), 256>>>(big, adj, ah, al, deg);
        // gi = agg0 @ Wc + deg*bc + bih
        gemm_tc<<<dim3(768/128, BN/128), 256>>>(ah, al, Wcch, Wccl,
            gru_bih, deg, bc, gi, nullptr, nullptr, BN, 768, Hn, 0);
        gru<<<BN, 256>>>(gi, big, h, hh, hl);
    }

    readout<<<1, 256>>>(h, ro_W1, ro_b1, ro_W2, ro_b2, (float*)d_out);
}

// round 5
// speedup vs baseline: 1.1562x; 1.1562x over previous
#include <cuda_runtime.h>
#include <cuda_bf16.h>
#include <math.h>
#include <stdint.h>

// Shapes: B=4, N=256, F=64, H=256, A=16, T=3
#define Bn 4
#define Nn 256
#define Fn 64
#define Hn 256
#define An 16
#define Tn 3
#define BN 1024
#define NC 1280

// ---------------- scratch (device globals) -----------------------------------
__device__ float d_h   [BN*Hn];
__device__ float d_big [BN*NC];     // [hi+b1 | hj | gh+bhh]; reused as pre-MLP tmp
__device__ float d_agg0[BN*Hn];
__device__ float d_deg [BN];
__device__ float d_gi  [BN*3*Hn];
__device__ float d_Wc  [Hn*3*Hn];   // msg_W2 @ gru_Wih
__device__ float d_bc  [3*Hn];      // msg_b2 @ gru_Wih
__device__ float d_Wcat[Hn*NC];     // [W1_i | W1_j | Whh]
__device__ float d_bcat[NC];

// ---------------- fp32 GEMM, 64x64 tile, 128 thr, double-buffered ------------
// C = f(A@B + bias + rowS*colV). A: MxK row-major, B: KxN row-major.
// M,N multiples of 64; K multiple of 16.
__device__ __forceinline__ void cpa16(void* s, const void* g) {
    uint32_t sa = (uint32_t)__cvta_generic_to_shared(s);
    asm volatile("cp.async.ca.shared.global [%0], [%1], 16;" :: "r"(sa), "l"(g));
}

__global__ void __launch_bounds__(128)
gemm64d(const float* __restrict__ A, const float* __restrict__ Bm,
        const float* __restrict__ bias, float* __restrict__ C,
        int M, int N, int K, int doRelu,
        const float* __restrict__ rowS, const float* __restrict__ colV)
{
    __shared__ __align__(16) float As[2][16][68];   // [buf][k][m], pad 68 (16B-aligned rows)
    __shared__ __align__(16) float Bs[2][16][64];   // [buf][k][n]

    int tid = threadIdx.x;
    int l = tid & 31, w = tid >> 5;
    int wm = w >> 1, wn = w & 1;                    // warp grid 2x2, 32x32 each
    int rg = l >> 2, cg = l & 3;                    // thread: 4 rows x (4+4) cols
    int row0 = blockIdx.y * 64, col0 = blockIdx.x * 64;

    // A loader: 256 float4 over 64 rows x 4 quads; 2 per thread
    int ar0 = tid >> 2,         ak0 = (tid & 3) << 2;       // idx = tid
    int ar1 = (tid + 128) >> 2, ak1 = ((tid + 128) & 3) << 2;
    // B loader (cp.async): 256 float4: k = idx>>4, n4 = (idx&15)*4
    int bk0 = tid >> 4,         bn0 = (tid & 15) << 2;
    int bk1 = (tid + 128) >> 4, bn1 = ((tid + 128) & 15) << 2;

    const float* Ab = A + (size_t)row0 * K;
    const float* Bb = Bm + col0;

    float acc[4][8];
    #pragma unroll
    for (int i = 0; i < 4; i++)
        #pragma unroll
        for (int j = 0; j < 8; j++) acc[i][j] = 0.f;

    // prologue: chunk 0
    float4 a0 = *(const float4*)(Ab + (size_t)ar0 * K + ak0);
    float4 a1 = *(const float4*)(Ab + (size_t)ar1 * K + ak1);
    As[0][ak0+0][ar0] = a0.x; As[0][ak0+1][ar0] = a0.y; As[0][ak0+2][ar0] = a0.z; As[0][ak0+3][ar0] = a0.w;
    As[0][ak1+0][ar1] = a1.x; As[0][ak1+1][ar1] = a1.y; As[0][ak1+2][ar1] = a1.z; As[0][ak1+3][ar1] = a1.w;
    cpa16(&Bs[0][bk0][bn0], Bb + (size_t)bk0 * N + bn0);
    cpa16(&Bs[0][bk1][bn1], Bb + (size_t)bk1 * N + bn1);
    asm volatile("cp.async.commit_group;");

    int nch = K >> 4;
    for (int ch = 0; ch < nch; ch++) {
        asm volatile("cp.async.wait_group 0;");
        __syncthreads();
        int buf = ch & 1, nb = buf ^ 1;
        int kn = (ch + 1) << 4;

        if (ch + 1 < nch) {   // LDG next A, cp.async next B (hidden under FFMAs)
            a0 = *(const float4*)(Ab + (size_t)ar0 * K + kn + ak0);
            a1 = *(const float4*)(Ab + (size_t)ar1 * K + kn + ak1);
            cpa16(&Bs[nb][bk0][bn0], Bb + (size_t)(kn + bk0) * N + bn0);
            cpa16(&Bs[nb][bk1][bn1], Bb + (size_t)(kn + bk1) * N + bn1);
            asm volatile("cp.async.commit_group;");
        }

        #pragma unroll
        for (int k = 0; k < 16; k++) {
            float4 av = *(float4*)&As[buf][k][wm * 32 + rg * 4];
            float4 b0 = *(float4*)&Bs[buf][k][wn * 32 + cg * 4];
            float4 b1 = *(float4*)&Bs[buf][k][wn * 32 + cg * 4 + 16];
            acc[0][0] += av.x*b0.x; acc[0][1] += av.x*b0.y; acc[0][2] += av.x*b0.z; acc[0][3] += av.x*b0.w;
            acc[0][4] += av.x*b1.x; acc[0][5] += av.x*b1.y; acc[0][6] += av.x*b1.z; acc[0][7] += av.x*b1.w;
            acc[1][0] += av.y*b0.x; acc[1][1] += av.y*b0.y; acc[1][2] += av.y*b0.z; acc[1][3] += av.y*b0.w;
            acc[1][4] += av.y*b1.x; acc[1][5] += av.y*b1.y; acc[1][6] += av.y*b1.z; acc[1][7] += av.y*b1.w;
            acc[2][0] += av.z*b0.x; acc[2][1] += av.z*b0.y; acc[2][2] += av.z*b0.z; acc[2][3] += av.z*b0.w;
            acc[2][4] += av.z*b1.x; acc[2][5] += av.z*b1.y; acc[2][6] += av.z*b1.z; acc[2][7] += av.z*b1.w;
            acc[3][0] += av.w*b0.x; acc[3][1] += av.w*b0.y; acc[3][2] += av.w*b0.z; acc[3][3] += av.w*b0.w;
            acc[3][4] += av.w*b1.x; acc[3][5] += av.w*b1.y; acc[3][6] += av.w*b1.z; acc[3][7] += av.w*b1.w;
        }

        if (ch + 1 < nch) {   // STS next A after compute (LDG has landed)
            As[nb][ak0+0][ar0] = a0.x; As[nb][ak0+1][ar0] = a0.y;
            As[nb][ak0+2][ar0] = a0.z; As[nb][ak0+3][ar0] = a0.w;
            As[nb][ak1+0][ar1] = a1.x; As[nb][ak1+1][ar1] = a1.y;
            As[nb][ak1+2][ar1] = a1.z; As[nb][ak1+3][ar1] = a1.w;
        }
    }

    // epilogue
    int c0 = col0 + wn * 32 + cg * 4;
    float4 bias0 = {0,0,0,0}, bias1 = {0,0,0,0};
    float4 cv0 = {0,0,0,0}, cv1 = {0,0,0,0};
    if (bias) { bias0 = *(const float4*)(bias + c0); bias1 = *(const float4*)(bias + c0 + 16); }
    if (rowS) { cv0 = *(const float4*)(colV + c0); cv1 = *(const float4*)(colV + c0 + 16); }

    #pragma unroll
    for (int i = 0; i < 4; i++) {
        int r = row0 + wm * 32 + rg * 4 + i;
        float rs = rowS ? rowS[r] : 0.f;
        float4 v0, v1;
        v0.x = acc[i][0] + bias0.x + rs * cv0.x;
        v0.y = acc[i][1] + bias0.y + rs * cv0.y;
        v0.z = acc[i][2] + bias0.z + rs * cv0.z;
        v0.w = acc[i][3] + bias0.w + rs * cv0.w;
        v1.x = acc[i][4] + bias1.x + rs * cv1.x;
        v1.y = acc[i][5] + bias1.y + rs * cv1.y;
        v1.z = acc[i][6] + bias1.z + rs * cv1.z;
        v1.w = acc[i][7] + bias1.w + rs * cv1.w;
        if (doRelu) {
            v0.x = fmaxf(v0.x, 0.f); v0.y = fmaxf(v0.y, 0.f); v0.z = fmaxf(v0.z, 0.f); v0.w = fmaxf(v0.w, 0.f);
            v1.x = fmaxf(v1.x, 0.f); v1.y = fmaxf(v1.y, 0.f); v1.z = fmaxf(v1.z, 0.f); v1.w = fmaxf(v1.w, 0.f);
        }
        *(float4*)(C + (size_t)r * N + c0)      = v0;
        *(float4*)(C + (size_t)r * N + c0 + 16) = v1;
    }
}

// ---------------- weight repack: Wcat = [W1_i | W1_j | Whh], bcat ------------
__global__ void repack(const float* __restrict__ msgW1, const float* __restrict__ Whh,
                       const float* __restrict__ msgb1, const float* __restrict__ bhh,
                       float* __restrict__ Wcat, float* __restrict__ bcat)
{
    int idx = blockIdx.x * 256 + threadIdx.x;        // over Hn*NC
    int k = idx / NC, n = idx % NC;
    float v;
    if (n < 256)       v = msgW1[(size_t)k * Hn + n];
    else if (n < 512)  v = msgW1[(size_t)(256 + k) * Hn + (n - 256)];
    else               v = Whh[(size_t)k * 768 + (n - 512)];
    Wcat[idx] = v;
    if (idx < NC)
        bcat[idx] = idx < 256 ? msgb1[idx] : (idx < 512 ? 0.f : bhh[idx - 512]);
}

// ---------------- E-aggregation ----------------------------------------------
// agg0[b,i,h] = sum_j adj * relu(hi'[i,h] + hj[j,h]); hi' at big[:,0:256]
#define IT 8
__global__ void eagg(const float* __restrict__ big, const int* __restrict__ adj,
                     float* __restrict__ agg0, float* __restrict__ deg)
{
    int b  = blockIdx.y;
    int i0 = blockIdx.x * IT;
    int h  = threadIdx.x;

    __shared__ float adjf[Nn][IT];

    float hir[IT], acc[IT];
    #pragma unroll
    for (int t = 0; t < IT; t++) {
        adjf[h][t] = (float)adj[((size_t)(b * Nn + i0 + t)) * Nn + h];
        hir[t] = big[((size_t)(b * Nn + i0 + t)) * NC + h];
        acc[t] = 0.f;
    }
    __syncthreads();

    const float* hjb = big + (size_t)b * Nn * NC + 256;
    #pragma unroll 2
    for (int j = 0; j < Nn; j++) {
        float hjv = hjb[(size_t)j * NC + h];
        float4 a04 = *(float4*)&adjf[j][0];
        float4 a47 = *(float4*)&adjf[j][4];
        acc[0] += a04.x * fmaxf(hir[0] + hjv, 0.f);
        acc[1] += a04.y * fmaxf(hir[1] + hjv, 0.f);
        acc[2] += a04.z * fmaxf(hir[2] + hjv, 0.f);
        acc[3] += a04.w * fmaxf(hir[3] + hjv, 0.f);
        acc[4] += a47.x * fmaxf(hir[4] + hjv, 0.f);
        acc[5] += a47.y * fmaxf(hir[5] + hjv, 0.f);
        acc[6] += a47.z * fmaxf(hir[6] + hjv, 0.f);
        acc[7] += a47.w * fmaxf(hir[7] + hjv, 0.f);
    }

    #pragma unroll
    for (int t = 0; t < IT; t++)
        agg0[((size_t)(b * Nn + i0 + t)) * Hn + h] = acc[t];

    if (h < IT) {
        float s = 0.f;
        for (int j = 0; j < Nn; j++) s += adjf[j][h];
        deg[b * Nn + i0 + h] = s;
    }
}

// ---------------- bc = msg_b2 @ gru_Wih (one warp per output) ----------------
__global__ void bck(const float* __restrict__ b2, const float* __restrict__ Wih,
                    float* __restrict__ bc)
{
    int warp = (blockIdx.x * blockDim.x + threadIdx.x) >> 5;
    int lane = threadIdx.x & 31;
    float s = 0.f;
    for (int k = lane; k < Hn; k += 32)
        s += b2[k] * Wih[(size_t)k * 768 + warp];
    #pragma unroll
    for (int o = 16; o; o >>= 1) s += __shfl_xor_sync(0xffffffffu, s, o);
    if (lane == 0) bc[warp] = s;
}

// ---------------- GRU elementwise update -------------------------------------
__global__ void gru(const float* __restrict__ gi, const float* __restrict__ big,
                    float* __restrict__ h)
{
    int idx = blockIdx.x * 256 + threadIdx.x;
    int m = idx >> 8, c = idx & 255;
    const float* gim = gi  + (size_t)m * 768;
    const float* ghm = big + (size_t)m * NC + 512;
    float ir = gim[c], iz = gim[c + 256], in = gim[c + 512];
    float hr = ghm[c], hz = ghm[c + 256], hn = ghm[c + 512];
    float r = 1.f / (1.f + __expf(-(ir + hr)));
    float z = 1.f / (1.f + __expf(-(iz + hz)));
    float n = tanhf(in + r * hn);
    h[idx] = (1.f - z) * n + z * h[idx];
}

// ---------------- readout ----------------------------------------------------
__global__ void readout(const float* __restrict__ h,
                        const float* __restrict__ W1, const float* __restrict__ b1,
                        const float* __restrict__ W2, const float* __restrict__ b2,
                        float* __restrict__ out)
{
    __shared__ float gsh[Bn][Hn];
    __shared__ float hsh[Bn][Hn];
    int t = threadIdx.x;
    for (int b = 0; b < Bn; b++) {
        float s = 0.f;
        for (int i = 0; i < Nn; i++) s += h[((size_t)(b * Nn + i)) * Hn + t];
        gsh[b][t] = s;
    }
    __syncthreads();
    for (int b = 0; b < Bn; b++) {
        float s = b1[t];
        for (int k = 0; k < Hn; k++) s += gsh[b][k] * W1[(size_t)k * Hn + t];
        hsh[b][t] = fmaxf(s, 0.f);
    }
    __syncthreads();
    if (t < Bn * An) {
        int b = t >> 4, a = t & 15;
        float s = b2[a];
        for (int k = 0; k < Hn; k++) s += hsh[b][k] * W2[(size_t)k * An + a];
        out[b * An + a] = s;
    }
}

// ---------------- host launch ------------------------------------------------
extern "C" void kernel_launch(void* const* d_in, const int* in_sizes, int n_in,
                              void* d_out, int out_size)
{
    const float* X       = (const float*)d_in[0];
    const int*   adj     = (const int*)  d_in[1];
    const float* pre_W1  = (const float*)d_in[2];
    const float* pre_b1  = (const float*)d_in[3];
    const float* pre_W2  = (const float*)d_in[4];
    const float* pre_b2  = (const float*)d_in[5];
    const float* msg_W1  = (const float*)d_in[6];
    const float* msg_b1  = (const float*)d_in[7];
    const float* msg_W2  = (const float*)d_in[8];
    const float* msg_b2  = (const float*)d_in[9];
    const float* gru_Wih = (const float*)d_in[10];
    const float* gru_Whh = (const float*)d_in[11];
    const float* gru_bih = (const float*)d_in[12];
    const float* gru_bhh = (const float*)d_in[13];
    const float* ro_W1   = (const float*)d_in[14];
    const float* ro_b1   = (const float*)d_in[15];
    const float* ro_W2   = (const float*)d_in[16];
    const float* ro_b2   = (const float*)d_in[17];

    float *h, *big, *agg0, *deg, *gi, *Wc, *bc, *Wcat, *bcat;
    cudaGetSymbolAddress((void**)&h,    d_h);
    cudaGetSymbolAddress((void**)&big,  d_big);
    cudaGetSymbolAddress((void**)&agg0, d_agg0);
    cudaGetSymbolAddress((void**)&deg,  d_deg);
    cudaGetSymbolAddress((void**)&gi,   d_gi);
    cudaGetSymbolAddress((void**)&Wc,   d_Wc);
    cudaGetSymbolAddress((void**)&bc,   d_bc);
    cudaGetSymbolAddress((void**)&Wcat, d_Wcat);
    cudaGetSymbolAddress((void**)&bcat, d_bcat);

    // one-time: repack + composed weight
    repack<<<Hn * NC / 256, 256>>>(msg_W1, gru_Whh, msg_b1, gru_bhh, Wcat, bcat);
    gemm64d<<<dim3(768/64, Hn/64), 128>>>(msg_W2, gru_Wih, nullptr, Wc, Hn, 768, Hn, 0, nullptr, nullptr);
    bck<<<96, 256>>>(msg_b2, gru_Wih, bc);

    // pre-MLP: h = relu(X@W1+b1) @ W2 + b2   (big reused as temp)
    gemm64d<<<dim3(Hn/64, BN/64), 128>>>(X, pre_W1, pre_b1, big, BN, Hn, Fn, 1, nullptr, nullptr);
    gemm64d<<<dim3(Hn/64, BN/64), 128>>>(big, pre_W2, pre_b2, h, BN, Hn, Hn, 0, nullptr, nullptr);

    for (int it = 0; it < Tn; it++) {
        // [hi+b1 | hj | gh+bhh] = h @ Wcat + bcat
        gemm64d<<<dim3(NC/64, BN/64), 128>>>(h, Wcat, bcat, big, BN, NC, Hn, 0, nullptr, nullptr);
        eagg<<<dim3(Nn/IT, Bn), 256>>>(big, adj, agg0, deg);
        // gi = agg0 @ Wc + deg*bc + bih
        gemm64d<<<dim3(768/64, BN/64), 128>>>(agg0, Wc, gru_bih, gi, BN, 768, Hn, 0, deg, bc);
        gru<<<BN, 256>>>(gi, big, h);
    }

    readout<<<1, 256>>>(h, ro_W1, ro_b1, ro_W2, ro_b2, (float*)d_out);
}

// round 6
// speedup vs baseline: 1.1969x; 1.0352x over previous
#include <cuda_runtime.h>
#include <cuda_bf16.h>
#include <math.h>
#include <stdint.h>

// Shapes: B=4, N=256, F=64, H=256, A=16, T=3
#define Bn 4
#define Nn 256
#define Fn 64
#define Hn 256
#define An 16
#define Tn 3
#define BN 1024
#define NC 1280

typedef unsigned long long u64;

// ---------------- scratch (device globals) -----------------------------------
__device__ float d_h   [BN*Hn];
__device__ float d_big [BN*NC];     // [hi+b1 | hj | gh+bhh]; reused as pre-MLP tmp
__device__ float d_agg0[BN*Hn];
__device__ float d_deg [BN];
__device__ float d_gi  [BN*3*Hn];
__device__ float d_Wc  [Hn*3*Hn];   // msg_W2 @ gru_Wih
__device__ float d_bc  [3*Hn];      // msg_b2 @ gru_Wih
__device__ float d_Wcat[Hn*NC];     // [W1_i | W1_j | Whh]
__device__ float d_bcat[NC];

// ---------------- f32x2 helpers ----------------------------------------------
#define FMA2(acc, a, b) \
    asm("fma.rn.f32x2 %0, %1, %2, %0;" : "+l"(acc) : "l"(a), "l"(b))
#define PACKDUP(d, s) \
    asm("mov.b64 %0, {%1, %1};" : "=l"(d) : "f"(s))
#define UNPACK2(lo, hi, s) \
    asm("mov.b64 {%0, %1}, %2;" : "=f"(lo), "=f"(hi) : "l"(s))

__device__ __forceinline__ void cpa16(void* s, const void* g) {
    uint32_t sa = (uint32_t)__cvta_generic_to_shared(s);
    asm volatile("cp.async.ca.shared.global [%0], [%1], 16;" :: "r"(sa), "l"(g));
}

// ---------------- fp32 GEMM, 64x64 tile, 128 thr, FFMA2 inner loop -----------
// C = f(A@B + bias + rowS*colV). A: MxK row-major, B: KxN row-major.
// M,N multiples of 64; K multiple of 16.
__global__ void __launch_bounds__(128)
gemm64d(const float* __restrict__ A, const float* __restrict__ Bm,
        const float* __restrict__ bias, float* __restrict__ C,
        int M, int N, int K, int doRelu,
        const float* __restrict__ rowS, const float* __restrict__ colV)
{
    __shared__ __align__(16) float As[2][16][68];   // [buf][k][m]
    __shared__ __align__(16) float Bs[2][16][64];   // [buf][k][n]

    int tid = threadIdx.x;
    int l = tid & 31, w = tid >> 5;
    int wm = w >> 1, wn = w & 1;                    // warp grid 2x2, 32x32 each
    int rg = l >> 2, cg = l & 3;                    // thread: 4 rows x (4+4) cols
    int row0 = blockIdx.y * 64, col0 = blockIdx.x * 64;

    int ar0 = tid >> 2,         ak0 = (tid & 3) << 2;
    int ar1 = (tid + 128) >> 2, ak1 = ((tid + 128) & 3) << 2;
    int bk0 = tid >> 4,         bn0 = (tid & 15) << 2;
    int bk1 = (tid + 128) >> 4, bn1 = ((tid + 128) & 15) << 2;

    const float* Ab = A + (size_t)row0 * K;
    const float* Bb = Bm + col0;

    // acc[i][j]: row i (4 rows), j -> col pairs {0,1},{2,3},{16,17},{18,19} rel. to c0
    u64 acc[4][4];
    #pragma unroll
    for (int i = 0; i < 4; i++)
        #pragma unroll
        for (int j = 0; j < 4; j++) acc[i][j] = 0ull;   // (0.f, 0.f)

    // prologue: chunk 0
    float4 a0 = *(const float4*)(Ab + (size_t)ar0 * K + ak0);
    float4 a1 = *(const float4*)(Ab + (size_t)ar1 * K + ak1);
    As[0][ak0+0][ar0] = a0.x; As[0][ak0+1][ar0] = a0.y; As[0][ak0+2][ar0] = a0.z; As[0][ak0+3][ar0] = a0.w;
    As[0][ak1+0][ar1] = a1.x; As[0][ak1+1][ar1] = a1.y; As[0][ak1+2][ar1] = a1.z; As[0][ak1+3][ar1] = a1.w;
    cpa16(&Bs[0][bk0][bn0], Bb + (size_t)bk0 * N + bn0);
    cpa16(&Bs[0][bk1][bn1], Bb + (size_t)bk1 * N + bn1);
    asm volatile("cp.async.commit_group;");

    int nch = K >> 4;
    for (int ch = 0; ch < nch; ch++) {
        asm volatile("cp.async.wait_group 0;");
        __syncthreads();
        int buf = ch & 1, nb = buf ^ 1;
        int kn = (ch + 1) << 4;

        if (ch + 1 < nch) {   // LDG next A, cp.async next B (hidden under FMAs)
            a0 = *(const float4*)(Ab + (size_t)ar0 * K + kn + ak0);
            a1 = *(const float4*)(Ab + (size_t)ar1 * K + kn + ak1);
            cpa16(&Bs[nb][bk0][bn0], Bb + (size_t)(kn + bk0) * N + bn0);
            cpa16(&Bs[nb][bk1][bn1], Bb + (size_t)(kn + bk1) * N + bn1);
            asm volatile("cp.async.commit_group;");
        }

        #pragma unroll
        for (int k = 0; k < 16; k++) {
            float4 av = *(float4*)&As[buf][k][wm * 32 + rg * 4];
            ulonglong2 bq0 = *(ulonglong2*)&Bs[buf][k][wn * 32 + cg * 4];
            ulonglong2 bq1 = *(ulonglong2*)&Bs[buf][k][wn * 32 + cg * 4 + 16];
            u64 ad0, ad1, ad2, ad3;
            PACKDUP(ad0, av.x); PACKDUP(ad1, av.y); PACKDUP(ad2, av.z); PACKDUP(ad3, av.w);
            FMA2(acc[0][0], ad0, bq0.x); FMA2(acc[0][1], ad0, bq0.y);
            FMA2(acc[0][2], ad0, bq1.x); FMA2(acc[0][3], ad0, bq1.y);
            FMA2(acc[1][0], ad1, bq0.x); FMA2(acc[1][1], ad1, bq0.y);
            FMA2(acc[1][2], ad1, bq1.x); FMA2(acc[1][3], ad1, bq1.y);
            FMA2(acc[2][0], ad2, bq0.x); FMA2(acc[2][1], ad2, bq0.y);
            FMA2(acc[2][2], ad2, bq1.x); FMA2(acc[2][3], ad2, bq1.y);
            FMA2(acc[3][0], ad3, bq0.x); FMA2(acc[3][1], ad3, bq0.y);
            FMA2(acc[3][2], ad3, bq1.x); FMA2(acc[3][3], ad3, bq1.y);
        }

        if (ch + 1 < nch) {   // STS next A after compute (LDG has landed)
            As[nb][ak0+0][ar0] = a0.x; As[nb][ak0+1][ar0] = a0.y;
            As[nb][ak0+2][ar0] = a0.z; As[nb][ak0+3][ar0] = a0.w;
            As[nb][ak1+0][ar1] = a1.x; As[nb][ak1+1][ar1] = a1.y;
            As[nb][ak1+2][ar1] = a1.z; As[nb][ak1+3][ar1] = a1.w;
        }
    }

    // epilogue
    int c0 = col0 + wn * 32 + cg * 4;
    float4 bias0 = {0,0,0,0}, bias1 = {0,0,0,0};
    float4 cv0 = {0,0,0,0}, cv1 = {0,0,0,0};
    if (bias) { bias0 = *(const float4*)(bias + c0); bias1 = *(const float4*)(bias + c0 + 16); }
    if (rowS) { cv0 = *(const float4*)(colV + c0); cv1 = *(const float4*)(colV + c0 + 16); }

    #pragma unroll
    for (int i = 0; i < 4; i++) {
        int r = row0 + wm * 32 + rg * 4 + i;
        float rs = rowS ? rowS[r] : 0.f;
        float4 v0, v1;
        UNPACK2(v0.x, v0.y, acc[i][0]);
        UNPACK2(v0.z, v0.w, acc[i][1]);
        UNPACK2(v1.x, v1.y, acc[i][2]);
        UNPACK2(v1.z, v1.w, acc[i][3]);
        v0.x += bias0.x + rs * cv0.x; v0.y += bias0.y + rs * cv0.y;
        v0.z += bias0.z + rs * cv0.z; v0.w += bias0.w + rs * cv0.w;
        v1.x += bias1.x + rs * cv1.x; v1.y += bias1.y + rs * cv1.y;
        v1.z += bias1.z + rs * cv1.z; v1.w += bias1.w + rs * cv1.w;
        if (doRelu) {
            v0.x = fmaxf(v0.x, 0.f); v0.y = fmaxf(v0.y, 0.f); v0.z = fmaxf(v0.z, 0.f); v0.w = fmaxf(v0.w, 0.f);
            v1.x = fmaxf(v1.x, 0.f); v1.y = fmaxf(v1.y, 0.f); v1.z = fmaxf(v1.z, 0.f); v1.w = fmaxf(v1.w, 0.f);
        }
        *(float4*)(C + (size_t)r * N + c0)      = v0;
        *(float4*)(C + (size_t)r * N + c0 + 16) = v1;
    }
}

// ---------------- weight repack: Wcat = [W1_i | W1_j | Whh], bcat ------------
__global__ void repack(const float* __restrict__ msgW1, const float* __restrict__ Whh,
                       const float* __restrict__ msgb1, const float* __restrict__ bhh,
                       float* __restrict__ Wcat, float* __restrict__ bcat)
{
    int idx = blockIdx.x * 256 + threadIdx.x;        // over Hn*NC
    int k = idx / NC, n = idx % NC;
    float v;
    if (n < 256)       v = msgW1[(size_t)k * Hn + n];
    else if (n < 512)  v = msgW1[(size_t)(256 + k) * Hn + (n - 256)];
    else               v = Whh[(size_t)k * 768 + (n - 512)];
    Wcat[idx] = v;
    if (idx < NC)
        bcat[idx] = idx < 256 ? msgb1[idx] : (idx < 512 ? 0.f : bhh[idx - 512]);
}

// ---------------- E-aggregation ----------------------------------------------
// agg0[b,i,h] = sum_j adj * relu(hi'[i,h] + hj[j,h]); hi' at big[:,0:256]
#define IT 8
__global__ void eagg(const float* __restrict__ big, const int* __restrict__ adj,
                     float* __restrict__ agg0, float* __restrict__ deg)
{
    int b  = blockIdx.y;
    int i0 = blockIdx.x * IT;
    int h  = threadIdx.x;

    __shared__ float adjf[Nn][IT];

    float hir[IT], acc[IT];
    #pragma unroll
    for (int t = 0; t < IT; t++) {
        adjf[h][t] = (float)adj[((size_t)(b * Nn + i0 + t)) * Nn + h];
        hir[t] = big[((size_t)(b * Nn + i0 + t)) * NC + h];
        acc[t] = 0.f;
    }
    __syncthreads();

    const float* hjb = big + (size_t)b * Nn * NC + 256;
    #pragma unroll 2
    for (int j = 0; j < Nn; j++) {
        float hjv = hjb[(size_t)j * NC + h];
        float4 a04 = *(float4*)&adjf[j][0];
        float4 a47 = *(float4*)&adjf[j][4];
        acc[0] += a04.x * fmaxf(hir[0] + hjv, 0.f);
        acc[1] += a04.y * fmaxf(hir[1] + hjv, 0.f);
        acc[2] += a04.z * fmaxf(hir[2] + hjv, 0.f);
        acc[3] += a04.w * fmaxf(hir[3] + hjv, 0.f);
        acc[4] += a47.x * fmaxf(hir[4] + hjv, 0.f);
        acc[5] += a47.y * fmaxf(hir[5] + hjv, 0.f);
        acc[6] += a47.z * fmaxf(hir[6] + hjv, 0.f);
        acc[7] += a47.w * fmaxf(hir[7] + hjv, 0.f);
    }

    #pragma unroll
    for (int t = 0; t < IT; t++)
        agg0[((size_t)(b * Nn + i0 + t)) * Hn + h] = acc[t];

    if (h < IT) {
        float s = 0.f;
        for (int j = 0; j < Nn; j++) s += adjf[j][h];
        deg[b * Nn + i0 + h] = s;
    }
}

// ---------------- bc = msg_b2 @ gru_Wih (one warp per output) ----------------
__global__ void bck(const float* __restrict__ b2, const float* __restrict__ Wih,
                    float* __restrict__ bc)
{
    int warp = (blockIdx.x * blockDim.x + threadIdx.x) >> 5;
    int lane = threadIdx.x & 31;
    float s = 0.f;
    for (int k = lane; k < Hn; k += 32)
        s += b2[k] * Wih[(size_t)k * 768 + warp];
    #pragma unroll
    for (int o = 16; o; o >>= 1) s += __shfl_xor_sync(0xffffffffu, s, o);
    if (lane == 0) bc[warp] = s;
}

// ---------------- GRU elementwise update -------------------------------------
__global__ void gru(const float* __restrict__ gi, const float* __restrict__ big,
                    float* __restrict__ h)
{
    int idx = blockIdx.x * 256 + threadIdx.x;
    int m = idx >> 8, c = idx & 255;
    const float* gim = gi  + (size_t)m * 768;
    const float* ghm = big + (size_t)m * NC + 512;
    float ir = gim[c], iz = gim[c + 256], in = gim[c + 512];
    float hr = ghm[c], hz = ghm[c + 256], hn = ghm[c + 512];
    float r = 1.f / (1.f + __expf(-(ir + hr)));
    float z = 1.f / (1.f + __expf(-(iz + hz)));
    float n = tanhf(in + r * hn);
    h[idx] = (1.f - z) * n + z * h[idx];
}

// ---------------- readout ----------------------------------------------------
__global__ void readout(const float* __restrict__ h,
                        const float* __restrict__ W1, const float* __restrict__ b1,
                        const float* __restrict__ W2, const float* __restrict__ b2,
                        float* __restrict__ out)
{
    __shared__ float gsh[Bn][Hn];
    __shared__ float hsh[Bn][Hn];
    int t = threadIdx.x;
    for (int b = 0; b < Bn; b++) {
        float s = 0.f;
        for (int i = 0; i < Nn; i++) s += h[((size_t)(b * Nn + i)) * Hn + t];
        gsh[b][t] = s;
    }
    __syncthreads();
    for (int b = 0; b < Bn; b++) {
        float s = b1[t];
        for (int k = 0; k < Hn; k++) s += gsh[b][k] * W1[(size_t)k * Hn + t];
        hsh[b][t] = fmaxf(s, 0.f);
    }
    __syncthreads();
    if (t < Bn * An) {
        int b = t >> 4, a = t & 15;
        float s = b2[a];
        for (int k = 0; k < Hn; k++) s += hsh[b][k] * W2[(size_t)k * An + a];
        out[b * An + a] = s;
    }
}

// ---------------- host launch ------------------------------------------------
extern "C" void kernel_launch(void* const* d_in, const int* in_sizes, int n_in,
                              void* d_out, int out_size)
{
    const float* X       = (const float*)d_in[0];
    const int*   adj     = (const int*)  d_in[1];
    const float* pre_W1  = (const float*)d_in[2];
    const float* pre_b1  = (const float*)d_in[3];
    const float* pre_W2  = (const float*)d_in[4];
    const float* pre_b2  = (const float*)d_in[5];
    const float* msg_W1  = (const float*)d_in[6];
    const float* msg_b1  = (const float*)d_in[7];
    const float* msg_W2  = (const float*)d_in[8];
    const float* msg_b2  = (const float*)d_in[9];
    const float* gru_Wih = (const float*)d_in[10];
    const float* gru_Whh = (const float*)d_in[11];
    const float* gru_bih = (const float*)d_in[12];
    const float* gru_bhh = (const float*)d_in[13];
    const float* ro_W1   = (const float*)d_in[14];
    const float* ro_b1   = (const float*)d_in[15];
    const float* ro_W2   = (const float*)d_in[16];
    const float* ro_b2   = (const float*)d_in[17];

    float *h, *big, *agg0, *deg, *gi, *Wc, *bc, *Wcat, *bcat;
    cudaGetSymbolAddress((void**)&h,    d_h);
    cudaGetSymbolAddress((void**)&big,  d_big);
    cudaGetSymbolAddress((void**)&agg0, d_agg0);
    cudaGetSymbolAddress((void**)&deg,  d_deg);
    cudaGetSymbolAddress((void**)&gi,   d_gi);
    cudaGetSymbolAddress((void**)&Wc,   d_Wc);
    cudaGetSymbolAddress((void**)&bc,   d_bc);
    cudaGetSymbolAddress((void**)&Wcat, d_Wcat);
    cudaGetSymbolAddress((void**)&bcat, d_bcat);

    // one-time: repack + composed weight
    repack<<<Hn * NC / 256, 256>>>(msg_W1, gru_Whh, msg_b1, gru_bhh, Wcat, bcat);
    gemm64d<<<dim3(768/64, Hn/64), 128>>>(msg_W2, gru_Wih, nullptr, Wc, Hn, 768, Hn, 0, nullptr, nullptr);
    bck<<<96, 256>>>(msg_b2, gru_Wih, bc);

    // pre-MLP: h = relu(X@W1+b1) @ W2 + b2   (big reused as temp)
    gemm64d<<<dim3(Hn/64, BN/64), 128>>>(X, pre_W1, pre_b1, big, BN, Hn, Fn, 1, nullptr, nullptr);
    gemm64d<<<dim3(Hn/64, BN/64), 128>>>(big, pre_W2, pre_b2, h, BN, Hn, Hn, 0, nullptr, nullptr);

    for (int it = 0; it < Tn; it++) {
        // [hi+b1 | hj | gh+bhh] = h @ Wcat + bcat
        gemm64d<<<dim3(NC/64, BN/64), 128>>>(h, Wcat, bcat, big, BN, NC, Hn, 0, nullptr, nullptr);
        eagg<<<dim3(Nn/IT, Bn), 256>>>(big, adj, agg0, deg);
        // gi = agg0 @ Wc + deg*bc + bih
        gemm64d<<<dim3(768/64, BN/64), 128>>>(agg0, Wc, gru_bih, gi, BN, 768, Hn, 0, deg, bc);
        gru<<<BN, 256>>>(gi, big, h);
    }

    readout<<<1, 256>>>(h, ro_W1, ro_b1, ro_W2, ro_b2, (float*)d_out);
}